// round 17
// baseline (speedup 1.0000x reference)
#include <cuda_runtime.h>
#include <cuda_bf16.h>
#include <cuda_fp16.h>

// Problem constants (fixed by dataset)
#define BB 2
#define CC 256
#define HH 56
#define WW 56
#define NN 64
#define MM 8
#define PP 7
#define R_PER_IMG (NN + NN*MM)        // 576
#define R_TOTAL   (BB * R_PER_IMG)    // 1152
#define MAXK 12
#define KCAP 10                       // true max support count

#define FS      68                    // fm smem row stride in uint2 (4ch fp16), EVEN
#define FROWB   (FS * 8)              // row stride in bytes (544, 16B-aligned)
#define FROWS   59                    // fm rows (ylo + span4 - 1 <= 58)
#define TROWS   56                    // tmp rows (writes bounded by 56)
#define TCLAMP  (55 * 7 + 6)          // max valid tmp cell index (391)

// Per-roi tables.
// g_meta[r*16 + row]: rows 0..6 = y (p): base | (cnt<<8), UNshifted.
//                     rows 7..13 = x (q): evenbase | (cnt'<<8), parity-shifted.
// g_yinfo[r] = ylo | (span4<<8)
// g_kmax[r*2+0] = exact max cnt_y (1..10); g_kmax[r*2+1] = max ceil(cnt_x'/2) (1..6)
// g_wgth[(r*14+row)*12 + k] = broadcast half2 (w,w), zero-padded to 12.
//   x rows are parity-shifted to match evenbase (16B-aligned tap pairs).
__device__ int      g_meta[R_TOTAL * 16];
__device__ int      g_yinfo[R_TOTAL];
__device__ int      g_kmax[R_TOTAL * 2];
__device__ __align__(16) unsigned g_wgth[R_TOTAL * 14 * MAXK];

// ---------------------------------------------------------------------------
// Kernel A: build sparse interpolation tables. Reference math exactly
// (fp32 accumulation of weights; final store rounded to broadcast half2).
// x-axis rows are stored parity-shifted so stage-1 tap PAIRS are 16B aligned.
// ---------------------------------------------------------------------------
__global__ void prep_kernel(const float* __restrict__ boxes,
                            const float* __restrict__ gts) {
    int t = blockIdx.x * blockDim.x + threadIdx.x;
    if (t >= R_TOTAL * 2) return;
    int r = t >> 1, a = t & 1;
    int b = r / R_PER_IMG, idx = r % R_PER_IMG;

    float x1, y1, x2, y2;
    if (idx < NN) {
        const float* bx = boxes + (b * NN + idx) * 4;
        x1 = bx[0]; y1 = bx[1]; x2 = bx[2]; y2 = bx[3];
    } else {
        int n = (idx - NN) >> 3, m = (idx - NN) & 7;
        const float* bx = boxes + (b * NN + n) * 4;
        const float* gx = gts   + (b * MM + m) * 4;
        x1 = fminf(bx[0], gx[0]); y1 = fminf(bx[1], gx[1]);
        x2 = fmaxf(bx[2], gx[2]); y2 = fmaxf(bx[3], gx[3]);
    }

    float start = a ? x1 : y1;
    float len   = fmaxf(a ? (x2 - x1) : (y2 - y1), 1.0f);
    const float dimf = 56.0f;
    const int   dim  = 56;

    float bin = len / 7.0f;
    int   g   = (int)ceilf(bin);
    float gf  = (float)g;
    float inv = 1.0f / gf;

    int lo_min = 1 << 20, hi_max = -1, km_acc = 1;
    for (int p = 0; p < 7; p++) {
        float acc[MAXK];
        #pragma unroll
        for (int k = 0; k < MAXK; k++) acc[k] = 0.0f;
        int base = -1, hi = -1;
        float c0 = start + (float)p * bin;
        for (int s = 0; s < 8; s++) {
            if (s >= g) break;
            float coord = c0 + ((float)s + 0.5f) * bin / gf;
            if (!(coord >= -1.0f && coord <= dimf)) continue;
            float c = fmaxf(coord, 0.0f);
            int low = (int)floorf(c);
            int high; float cv;
            if (low >= dim - 1) { low = dim - 1; high = dim - 1; cv = (float)low; }
            else                { high = low + 1; cv = c; }
            float l  = cv - (float)low;
            float wl = (1.0f - l) * inv;
            float wh = l * inv;
            if (base < 0) base = low;
            int d  = low  - base;
            int d2 = high - base;
            if (d  >= 0 && d  < MAXK) acc[d]  += wl;
            if (d2 >= 0 && d2 < MAXK) acc[d2] += wh;
            if (high > hi) hi = high;
        }
        int cnt = (base < 0) ? 0 : (hi - base + 1);
        if (base < 0) base = 0;
        if (cnt > KCAP) cnt = KCAP;
        if (base < lo_min) lo_min = base;
        if (base + cnt > hi_max) hi_max = base + cnt;

        int stbase = base, stcnt = cnt, shift = 0;
        if (a == 1) {                     // x: parity-shift to even base
            shift  = base & 1;
            stbase = base - shift;        // even
            stcnt  = cnt + shift;         // <= 11
            int kg = (stcnt + 1) >> 1;    // ceil(cnt'/2), 1..6
            if (kg < 1) kg = 1;
            if (kg > km_acc) km_acc = kg;
        } else {
            if (cnt > km_acc) km_acc = cnt;
        }
        g_meta[r * 16 + a * 7 + p] = stbase | (stcnt << 8);
        unsigned* wp = g_wgth + (size_t)((r * 14 + a * 7 + p)) * MAXK;
        #pragma unroll
        for (int k = 0; k < MAXK; k++) {
            float wv = (k >= shift && (k - shift) < MAXK) ? acc[k - shift] : 0.0f;
            if (a == 1 && k < shift) wv = 0.0f;
            unsigned hb = __half_as_ushort(__float2half_rn(wv));
            wp[k] = hb * 0x10001u;        // broadcast half2 (w, w)
        }
    }
    if (km_acc < 1) km_acc = 1;
    if (a == 0 && km_acc > KCAP) km_acc = KCAP;
    if (a == 1 && km_acc > 6)    km_acc = 6;
    g_kmax[r * 2 + a] = km_acc;
    if (a == 0) {
        int lo = lo_min, span = hi_max - lo_min;
        if (span < 1) { lo = 0; span = 1; }
        int span4 = (span + 3) & ~3;
        g_yinfo[r] = lo | (span4 << 8);
    }
}

// ---------------------------------------------------------------------------
// Helpers
// ---------------------------------------------------------------------------
__device__ __forceinline__ __half2 u2h(unsigned u) {
    return *reinterpret_cast<__half2*>(&u);
}
__device__ __forceinline__ unsigned h2u(__half2 h) {
    return *reinterpret_cast<unsigned*>(&h);
}
__device__ __forceinline__ unsigned ucomp(uint4 v, int i) {
    return i == 0 ? v.x : i == 1 ? v.y : i == 2 ? v.z : v.w;
}
__device__ __forceinline__ uint2 pack4h(float a, float b, float c, float d) {
    __half2 h01 = __floats2half2_rn(a, b);
    __half2 h23 = __floats2half2_rn(c, d);
    uint2 r;
    r.x = h2u(h01);
    r.y = h2u(h23);
    return r;
}

// ---------------------------------------------------------------------------
// Stage bodies. Masking entirely via zero-padded fp16 WEIGHTS over zeroed /
// finite pad data. Within-roi accumulation in half2 (HFMA2).
// Stage-1: KG aligned uint4 loads per lane (2 taps each): 1 LDS.128 + 4 HFMA2
// per tap pair. Stage-2: stride-7 uint2 taps, index clamped into finite tmp.
// ---------------------------------------------------------------------------
template<int KG>
__device__ __forceinline__ void s1loop(const char* fmb, uint2* tmpw,
        int ylo, int span4, int hsub, int qx, bool act1,
        int evenu, const unsigned* wph) {
    const uint4* w4 = (const uint4*)wph;
    uint4 wa = __ldg(w4);
    uint4 wb = (KG > 2) ? __ldg(w4 + 1) : make_uint4(0u, 0u, 0u, 0u);
    uint4 wc = (KG > 4) ? __ldg(w4 + 2) : make_uint4(0u, 0u, 0u, 0u);
    const int u4off = evenu >> 1;             // uint4 index within row
    #pragma unroll 2
    for (int hb = 0; hb < span4; hb += 4) {
        if (act1) {
            int h = hb + hsub;
            const uint4* row4 = (const uint4*)(fmb + (ylo + h) * FROWB) + u4off;
            __half2 a01 = u2h(0u), a23 = u2h(0u);
            #pragma unroll
            for (int kk = 0; kk < KG; kk++) {
                uint4 v = row4[kk];
                int i0 = 2 * kk, i1 = 2 * kk + 1;
                unsigned wA = (i0 < 4) ? ucomp(wa, i0)
                             : (i0 < 8) ? ucomp(wb, i0 - 4) : ucomp(wc, i0 - 8);
                unsigned wB = (i1 < 4) ? ucomp(wa, i1)
                             : (i1 < 8) ? ucomp(wb, i1 - 4) : ucomp(wc, i1 - 8);
                a01 = __hfma2(u2h(wA), u2h(v.x), a01);
                a23 = __hfma2(u2h(wA), u2h(v.y), a23);
                a01 = __hfma2(u2h(wB), u2h(v.z), a01);
                a23 = __hfma2(u2h(wB), u2h(v.w), a23);
            }
            tmpw[h * 7 + qx] = make_uint2(h2u(a01), h2u(a23));
        }
    }
}

template<int KM>
__device__ __forceinline__ void s2cell(const char* tb, int basei,
        const unsigned* wph, float2& s01, float2& s23) {
    const uint4* w4 = (const uint4*)wph;
    uint4 ua = __ldg(w4);
    uint4 ub = (KM > 4) ? __ldg(w4 + 1) : make_uint4(0u, 0u, 0u, 0u);
    uint4 uc = (KM > 8) ? __ldg(w4 + 2) : make_uint4(0u, 0u, 0u, 0u);
    __half2 h01 = u2h(0u), h23 = u2h(0u);
    #pragma unroll
    for (int k = 0; k < KM; k++) {
        unsigned wk = (k < 4) ? ucomp(ua, k)
                     : (k < 8) ? ucomp(ub, k - 4) : ucomp(uc, k - 8);
        int ai = basei + k * 7;
        if (ai > TCLAMP) ai = TCLAMP;     // zero-weight taps only
        uint2 tv = *(const uint2*)(tb + ai * 8);
        h01 = __hfma2(u2h(wk), u2h(tv.x), h01);
        h23 = __hfma2(u2h(wk), u2h(tv.y), h23);
    }
    s01 = __half22float2(h01);
    s23 = __half22float2(h23);
}

// ---------------------------------------------------------------------------
// Kernel B: one CTA per (channel-quad, image, n-eighth). fm 4ch fp16 packed
// in smem (59 rows x 68 stride, pads zeroed); tmp fp16 (56 rows), zero-init.
// 8 warps, one n each; per n: box roi + 8 ctx rois; roi-level accum fp32.
// smem 55.9KB + regs<=64  ->  4 CTAs/SM (32 warps).
// ---------------------------------------------------------------------------
__global__ void __launch_bounds__(256, 4)
roi_main_kernel(const float* __restrict__ fm, float* __restrict__ out) {
    const int cq = blockIdx.x;               // channel quad: c0 = 4*cq
    const int b  = blockIdx.y;
    const int nbase = blockIdx.z * 8;        // 8 n per CTA, one per warp

    __shared__ __align__(16) uint2 fm_s[FROWS * FS];   // 32096 B
    __shared__ __align__(16) uint2 tmp_s[8][TROWS * 7];// 25088 B

    const int tid = threadIdx.x;
    const int c0 = cq * 4;

    // ---- stage fm[b][c0..c0+3] packed fp16; zero ALL pad regions + tmp ----
    {
        const uint2 z2 = make_uint2(0u, 0u);
        for (int i = tid; i < 3 * FS; i += 256) fm_s[56 * FS + i] = z2;   // rows 56..58
        for (int i = tid; i < 56 * 12; i += 256) {                        // cols 56..67
            int h = i / 12, w = 56 + (i % 12);
            fm_s[h * FS + w] = z2;
        }
        uint2* tz = &tmp_s[0][0];
        for (int i = tid; i < 8 * TROWS * 7; i += 256) tz[i] = z2;        // tmp finite

        const float4* s0 = (const float4*)(fm + ((size_t)(b * CC + c0)     ) * (HH * WW));
        const float4* s1 = (const float4*)(fm + ((size_t)(b * CC + c0 + 1)) * (HH * WW));
        const float4* s2 = (const float4*)(fm + ((size_t)(b * CC + c0 + 2)) * (HH * WW));
        const float4* s3 = (const float4*)(fm + ((size_t)(b * CC + c0 + 3)) * (HH * WW));
        for (int i = tid; i < 784; i += 256) {
            float4 v0 = s0[i];
            float4 v1 = s1[i];
            float4 v2 = s2[i];
            float4 v3 = s3[i];
            int h = i / 14, w = (i % 14) * 4;
            uint2* d = &fm_s[h * FS + w];
            d[0] = pack4h(v0.x, v1.x, v2.x, v3.x);
            d[1] = pack4h(v0.y, v1.y, v2.y, v3.y);
            d[2] = pack4h(v0.z, v1.z, v2.z, v3.z);
            d[3] = pack4h(v0.w, v1.w, v2.w, v3.w);
        }
    }
    __syncthreads();

    const int wid  = tid >> 5;
    const int lane = tid & 31;
    uint2* tmpw = tmp_s[wid];
    const char* tb  = (const char*)tmpw;
    const char* fmb = (const char*)fm_s;

    // stage-1 lane mapping: lanes 0..27 -> (hsub, qx)
    const int qx   = lane % 7;
    const int hsub = lane / 7;
    const bool act1 = (lane < 28);

    // stage-2 cell mapping: cell0 = lane, cell1 = lane+32
    const int p0 = lane / 7,        q0 = lane % 7;
    const int p1 = (lane + 32) / 7, q1 = (lane + 32) % 7;
    const bool has1 = (lane + 32 < 49);

    const int n = nbase + wid;

    float4 acc0 = make_float4(0.f, 0.f, 0.f, 0.f);
    float4 acc1 = make_float4(0.f, 0.f, 0.f, 0.f);

    #pragma unroll 1
    for (int j = 0; j < 9; j++) {
        const int r = b * R_PER_IMG + ((j == 0) ? n : (NN + n * 8 + (j - 1)));
        const float wroi = (j == 0) ? 1.0f : 0.125f;
        const int yinfo = __ldg(&g_yinfo[r]);
        const int ylo   = yinfo & 0xFF;
        const int span4 = yinfo >> 8;
        const int ky    = __ldg(&g_kmax[r * 2]);
        const int kg    = __ldg(&g_kmax[r * 2 + 1]);   // 1..6 uint4 groups
        const int mbase = r * 16;
        const unsigned* whbase = g_wgth + (size_t)r * 168;

        // ---- stage 1: x-interp into tmp[h][q] (fp16 accum, uint4 taps) ----
        {
            int metax = __ldg(&g_meta[mbase + 7 + qx]);
            int evenu = metax & 0xFF;                  // even uint2 index
            const unsigned* wpx = whbase + (7 + qx) * 12;
            #define CS1(K) case K: s1loop<K>(fmb, tmpw, ylo, span4, hsub, qx, act1, evenu, wpx); break;
            switch (kg) {
                CS1(1) CS1(2) CS1(3) CS1(4) CS1(5)
                default: s1loop<6>(fmb, tmpw, ylo, span4, hsub, qx, act1, evenu, wpx); break;
            }
            #undef CS1
        }
        __syncwarp();

        // ---- stage 2: y-interp from tmp (fp16 accum, fp32 roi combine) ----
        {
            int meta0 = __ldg(&g_meta[mbase + p0]);
            int meta1 = has1 ? __ldg(&g_meta[mbase + p1]) : meta0;
            int base0 = ((meta0 & 0xFF) - ylo) * 7 + q0;
            int base1 = ((meta1 & 0xFF) - ylo) * 7 + (has1 ? q1 : q0);
            const unsigned* wp0 = whbase + p0 * 12;
            const unsigned* wp1 = whbase + (has1 ? p1 : p0) * 12;

            float2 s001, s023, s101, s123;
            #define CS2(K) case K: { s2cell<K>(tb, base0, wp0, s001, s023); \
                                     s2cell<K>(tb, base1, wp1, s101, s123); } break;
            switch (ky) {
                CS2(1) CS2(2) CS2(3) CS2(4) CS2(5)
                CS2(6) CS2(7) CS2(8) CS2(9)
                default: { s2cell<10>(tb, base0, wp0, s001, s023);
                           s2cell<10>(tb, base1, wp1, s101, s123); } break;
            }
            #undef CS2
            acc0.x += wroi * s001.x; acc0.y += wroi * s001.y;
            acc0.z += wroi * s023.x; acc0.w += wroi * s023.y;
            acc1.x += wroi * s101.x; acc1.y += wroi * s101.y;
            acc1.z += wroi * s123.x; acc1.w += wroi * s123.y;
        }
        __syncwarp();   // tmp reuse safety before next roi
    }

    // ---- store out[b][n][c][p][q], channels c0..c0+3 ----
    float* o = out + ((size_t)(b * NN + n) * CC + c0) * (PP * PP);
    o[lane]       = acc0.x;
    o[49 + lane]  = acc0.y;
    o[98 + lane]  = acc0.z;
    o[147 + lane] = acc0.w;
    if (has1) {
        o[lane + 32]       = acc1.x;
        o[49 + lane + 32]  = acc1.y;
        o[98 + lane + 32]  = acc1.z;
        o[147 + lane + 32] = acc1.w;
    }
}

// ---------------------------------------------------------------------------
extern "C" void kernel_launch(void* const* d_in, const int* in_sizes, int n_in,
                              void* d_out, int out_size) {
    const float* fm    = (const float*)d_in[0];
    const float* boxes = (const float*)d_in[1];
    const float* gts   = (const float*)d_in[2];
    float* out = (float*)d_out;

    prep_kernel<<<(R_TOTAL * 2 + 127) / 128, 128>>>(boxes, gts);

    dim3 grid(CC / 4, BB, 8);
    roi_main_kernel<<<grid, 256>>>(fm, out);
}